// round 11
// baseline (speedup 1.0000x reference)
#include <cuda_runtime.h>
#include <stdint.h>

#define D        256
#define MITEMS   16
#define TPB      256
#define NWARP    8
#define GRID     148
#define RPW      111           // rows per warp (148*8*111 >= 131072)
#define TILE     64            // rows per warp-tile
#define CHUNK    16            // dims per pipeline chunk (64 B per row)
#define NCH      16            // D / CHUNK
#define NBUF     4
#define QSTR     20            // staging row stride (floats): LDS.128 conflict-free
#define BUFW     (TILE * QSTR) // 1280 floats per buffer
#define RINGW    (NBUF * BUFW) // 5120 floats per warp ring
#define SM_MEM   (NWARP * RINGW)           // 40960: mem_rm offset
#define SM_PW    (SM_MEM + MITEMS * D)     // 45056: pw offset
#define PWSTR    8                          // per-row pw stride (4 w + idx + pad)
#define SMEM_FLOATS (SM_PW + NWARP * TILE * PWSTR)   // 49152 floats = 196608 B
#define SMEM_BYTES  (SMEM_FLOATS * 4)
#define NEG_BIG (-1e30f)

typedef unsigned long long u64;

__device__ __forceinline__ u64 pack2(float lo, float hi) {
    u64 r; asm("mov.b64 %0, {%1, %2};" : "=l"(r) : "f"(lo), "f"(hi)); return r;
}
__device__ __forceinline__ void unpack2(u64 v, float& lo, float& hi) {
    asm("mov.b64 {%0, %1}, %2;" : "=f"(lo), "=f"(hi) : "l"(v));
}
#define FMA2(d, a, b) asm("fma.rn.f32x2 %0, %1, %2, %0;" : "+l"(d) : "l"(a), "l"(b))
#define CP16(dst, src) \
    asm volatile("cp.async.cg.shared.global [%0], [%1], 16;" :: "r"(dst), "l"(src))
#define CPCOMMIT() asm volatile("cp.async.commit_group;")
#define CPWAIT(n)  asm volatile("cp.async.wait_group %0;" :: "n"(n))

__global__ void __launch_bounds__(TPB, 1) epm_kernel(
    const float* __restrict__ q,
    const float* __restrict__ mem,
    float* __restrict__ out_ret,
    float* __restrict__ out_max,
    int nrows)
{
    extern __shared__ __align__(16) float sh[];
    const int tid  = threadIdx.x;
    const int wid  = tid >> 5;
    const int lane = tid & 31;

    float* ring   = sh + wid * RINGW;
    float* mem_rm = sh + SM_MEM;
    float* pw     = sh + SM_PW + wid * TILE * PWSTR;
    const uint32_t ring_s = (uint32_t)__cvta_generic_to_shared(ring);

    // ---- block-cooperative: memory bank row-major into smem ----
    {
        const float4* s4 = (const float4*)mem;
        float4* d4 = (float4*)mem_rm;
        #pragma unroll
        for (int i = 0; i < (MITEMS * D / 4) / TPB; i++)   // 4 iters
            d4[tid + TPB * i] = s4[tid + TPB * i];
    }
    __syncthreads();    // the ONLY block barrier

    // ---- warp work assignment ----
    const int wg    = blockIdx.x * NWARP + wid;
    const int base  = wg * RPW;
    int count = nrows - base;
    if (count > RPW) count = RPW;

    // cp.async lane mapping within a 64-row tile chunk:
    const int rsub = lane >> 2;    // 0..7 (rows rsub + 8j)
    const int sub  = lane & 3;     // 16B slot within the 64B row segment

    if (count > 0) {
        for (int tb = 0; tb < count; tb += TILE) {
            const int tr    = min(TILE, count - tb);
            const int rowg0 = base + tb;

            // ---- prologue: issue chunks 0..2 into bufs 0..2 ----
            #pragma unroll
            for (int c0 = 0; c0 < 3; c0++) {
                #pragma unroll
                for (int j = 0; j < 8; j++) {
                    int rl = rsub + 8 * j;
                    if (rl < tr) {
                        const float* src = q + (size_t)(rowg0 + rl) * D + c0 * CHUNK + sub * 4;
                        uint32_t dst = ring_s +
                            (uint32_t)(c0 * BUFW + rl * QSTR + sub * 4) * 4u;
                        CP16(dst, src);
                    }
                }
                CPCOMMIT();
            }

            // ---- dot mainloop: warp-private ring, no block barriers ----
            u64 accA[MITEMS], accB[MITEMS], ssqA = 0ull, ssqB = 0ull;
            #pragma unroll
            for (int m = 0; m < MITEMS; m++) { accA[m] = 0ull; accB[m] = 0ull; }

            #pragma unroll 1
            for (int ct = 0; ct < NCH; ct++) {
                if (ct <= NCH - 3)      { CPWAIT(2); }
                else if (ct == NCH - 2) { CPWAIT(1); }
                else                    { CPWAIT(0); }
                __syncwarp();

                // refill the just-freed buffer (this warp finished reading it)
                if (ct + 3 < NCH) {
                    #pragma unroll
                    for (int j = 0; j < 8; j++) {
                        int rl = rsub + 8 * j;
                        if (rl < tr) {
                            const float* src = q + (size_t)(rowg0 + rl) * D
                                             + (ct + 3) * CHUNK + sub * 4;
                            uint32_t dst = ring_s +
                                (uint32_t)(((ct + 3) & 3) * BUFW + rl * QSTR + sub * 4) * 4u;
                            CP16(dst, src);
                        }
                    }
                    CPCOMMIT();
                }

                const float* qb = ring + (ct & 3) * BUFW;
                ulonglong2 qA[4], qB[4];
                #pragma unroll
                for (int g = 0; g < 4; g++) {
                    qA[g] = *(const ulonglong2*)(qb + lane * QSTR + 4 * g);
                    qB[g] = *(const ulonglong2*)(qb + (lane + 32) * QSTR + 4 * g);
                    FMA2(ssqA, qA[g].x, qA[g].x); FMA2(ssqA, qA[g].y, qA[g].y);
                    FMA2(ssqB, qB[g].x, qB[g].x); FMA2(ssqB, qB[g].y, qB[g].y);
                }
                #pragma unroll
                for (int m = 0; m < MITEMS; m++) {
                    const ulonglong2* mt = (const ulonglong2*)(mem_rm + m * D + ct * CHUNK);
                    ulonglong2 v0 = mt[0], v1 = mt[1], v2 = mt[2], v3 = mt[3]; // broadcast
                    FMA2(accA[m], v0.x, qA[0].x); FMA2(accA[m], v0.y, qA[0].y);
                    FMA2(accA[m], v1.x, qA[1].x); FMA2(accA[m], v1.y, qA[1].y);
                    FMA2(accA[m], v2.x, qA[2].x); FMA2(accA[m], v2.y, qA[2].y);
                    FMA2(accA[m], v3.x, qA[3].x); FMA2(accA[m], v3.y, qA[3].y);
                    FMA2(accB[m], v0.x, qB[0].x); FMA2(accB[m], v0.y, qB[0].y);
                    FMA2(accB[m], v1.x, qB[1].x); FMA2(accB[m], v1.y, qB[1].y);
                    FMA2(accB[m], v2.x, qB[2].x); FMA2(accB[m], v2.y, qB[2].y);
                    FMA2(accB[m], v3.x, qB[3].x); FMA2(accB[m], v3.y, qB[3].y);
                }
            }

            // ---- epilogue: 2 rows per lane -> pw (stride 8) + out_max ----
            #pragma unroll
            for (int r = 0; r < 2; r++) {
                int rl = lane + 32 * r;
                float s[MITEMS];
                #pragma unroll
                for (int m = 0; m < MITEMS; m++) {
                    float lo, hi; unpack2(r == 0 ? accA[m] : accB[m], lo, hi);
                    s[m] = lo + hi;
                }
                float sl, shi; unpack2(r == 0 ? ssqA : ssqB, sl, shi);
                float inv = rsqrtf(fmaxf(sl + shi, 1e-24f)) * 10.0f; // (1/|q|)/tau
                #pragma unroll
                for (int m = 0; m < MITEMS; m++) s[m] *= inv;

                float bw[4]; int bi[4];
                #pragma unroll
                for (int k = 0; k < 4; k++) {
                    float best = NEG_BIG; int b = 0;
                    #pragma unroll
                    for (int m = 0; m < MITEMS; m++)
                        if (s[m] > best) { best = s[m]; b = m; }  // first-index ties
                    bw[k] = best; bi[k] = b;
                    #pragma unroll
                    for (int m = 0; m < MITEMS; m++)
                        s[m] = (m == b) ? NEG_BIG : s[m];
                }
                float e1 = __expf(bw[1] - bw[0]);
                float e2 = __expf(bw[2] - bw[0]);
                float e3 = __expf(bw[3] - bw[0]);
                float rden = 1.0f / (1.0f + e1 + e2 + e3);

                if (rl < tr) {
                    float* Wr = pw + rl * PWSTR;
                    Wr[0] = rden;
                    Wr[1] = e1 * rden;
                    Wr[2] = e2 * rden;
                    Wr[3] = e3 * rden;
                    ((int*)Wr)[4] = bi[0] | (bi[1] << 4) | (bi[2] << 8) | (bi[3] << 12);
                    out_max[rowg0 + rl] = bw[0];
                }
            }
            __syncwarp();

            // ---- dense blend from registers: zero smem gathers ----
            // lane owns output floats [4*lane..+3] and [128+4*lane..+3]
            {
                ulonglong2 V[2 * MITEMS];     // acc regs are dead; compiler reuses
                const ulonglong2* mg = (const ulonglong2*)mem_rm;
                #pragma unroll
                for (int m = 0; m < MITEMS; m++) {
                    V[2 * m    ] = mg[m * (D / 4) + lane];
                    V[2 * m + 1] = mg[m * (D / 4) + 32 + lane];
                }

                #pragma unroll 2
                for (int j = 0; j < TILE; j++) {
                    if (j >= tr) break;
                    const float* Wr = pw + j * PWSTR;
                    float4 w4 = *(const float4*)Wr;      // broadcast, 1 wf
                    int pk = ((const int*)Wr)[4];        // broadcast

                    // expand sparse weights into dense packed 16-vector
                    u64 wv[MITEMS];
                    #pragma unroll
                    for (int m = 0; m < MITEMS; m++) wv[m] = 0ull;
                    wv[(pk      ) & 15] = pack2(w4.x, w4.x);
                    wv[(pk >> 4 ) & 15] = pack2(w4.y, w4.y);
                    wv[(pk >> 8 ) & 15] = pack2(w4.z, w4.z);
                    wv[(pk >> 12) & 15] = pack2(w4.w, w4.w);

                    u64 o0 = 0ull, o1 = 0ull, o2 = 0ull, o3 = 0ull;
                    #pragma unroll
                    for (int m = 0; m < MITEMS; m++) {
                        FMA2(o0, V[2 * m    ].x, wv[m]);
                        FMA2(o1, V[2 * m    ].y, wv[m]);
                        FMA2(o2, V[2 * m + 1].x, wv[m]);
                        FMA2(o3, V[2 * m + 1].y, wv[m]);
                    }
                    ulonglong2* op = (ulonglong2*)(out_ret + (size_t)(rowg0 + j) * D);
                    ulonglong2 v0; v0.x = o0; v0.y = o1;
                    ulonglong2 v1; v1.x = o2; v1.y = o3;
                    op[lane]      = v0;
                    op[32 + lane] = v1;
                }
            }
            __syncwarp();
        }
    }
}

extern "C" void kernel_launch(void* const* d_in, const int* in_sizes, int n_in,
                              void* d_out, int out_size)
{
    const float* q   = (const float*)d_in[0];
    const float* mem = (const float*)d_in[1];
    int nrows = in_sizes[0] / D;              // 131072
    float* out_ret = (float*)d_out;
    float* out_max = out_ret + (size_t)nrows * D;

    cudaFuncSetAttribute(epm_kernel,
                         cudaFuncAttributeMaxDynamicSharedMemorySize, SMEM_BYTES);

    epm_kernel<<<GRID, TPB, SMEM_BYTES>>>(q, mem, out_ret, out_max, nrows);
}

// round 12
// speedup vs baseline: 2.0526x; 2.0526x over previous
#include <cuda_runtime.h>
#include <stdint.h>

#define D        256
#define MITEMS   16
#define TPB      512
#define NWARP    16
#define GRID     148
#define RPW      56            // rows per warp: 148*16*56 = 132608 >= 131072
#define TILE     64            // staging capacity per tile (tr <= 56 used)
#define CHUNK    8             // dims per pipeline chunk (32 B per row)
#define NCH      32            // D / CHUNK
#define NBUF     3
#define QSTR     12            // staging row stride (floats): 48B, LDS.128 conflict-free
#define BUFW     (TILE * QSTR) // 768 floats per buffer
#define RINGW    (NBUF * BUFW) // 2304 floats per warp ring
#define SM_MT    (NWARP * RINGW)            // 36864: mem_t offset (item-pair transposed)
#define SM_RM    (SM_MT + MITEMS * D)       // 40960: mem_rm offset (row-major, blend)
#define SM_PW    (SM_RM + MITEMS * D)       // 45056: pw offset
#define PWSTR    8
#define SMEM_FLOATS (SM_PW + NWARP * TILE * PWSTR)   // 53248 floats = 212992 B
#define SMEM_BYTES  (SMEM_FLOATS * 4)
#define NEG_BIG (-1e30f)

typedef unsigned long long u64;

__device__ __forceinline__ u64 pack2(float lo, float hi) {
    u64 r; asm("mov.b64 %0, {%1, %2};" : "=l"(r) : "f"(lo), "f"(hi)); return r;
}
__device__ __forceinline__ void unpack2(u64 v, float& lo, float& hi) {
    asm("mov.b64 {%0, %1}, %2;" : "=f"(lo), "=f"(hi) : "l"(v));
}
#define FMA2(d, a, b) asm("fma.rn.f32x2 %0, %1, %2, %0;" : "+l"(d) : "l"(a), "l"(b))
#define CP16(dst, src) \
    asm volatile("cp.async.cg.shared.global [%0], [%1], 16;" :: "r"(dst), "l"(src))
#define CPCOMMIT() asm volatile("cp.async.commit_group;")
#define CPWAIT(n)  asm volatile("cp.async.wait_group %0;" :: "n"(n))

__global__ void __launch_bounds__(TPB, 1) epm_kernel(
    const float* __restrict__ q,
    const float* __restrict__ mem,
    float* __restrict__ out_ret,
    float* __restrict__ out_max,
    int nrows)
{
    extern __shared__ __align__(16) float sh[];
    const int tid  = threadIdx.x;
    const int wid  = tid >> 5;
    const int lane = tid & 31;

    float* ring   = sh + wid * RINGW;
    float* mem_t  = sh + SM_MT;     // [dim][16 items] (item pairs contiguous)
    float* mem_rm = sh + SM_RM;     // [item][256]
    float* pw     = sh + SM_PW + wid * TILE * PWSTR;
    const uint32_t ring_s = (uint32_t)__cvta_generic_to_shared(ring);

    // ---- warp work assignment (single tile per warp) ----
    const int base = (blockIdx.x * NWARP + wid) * RPW;
    int tr = nrows - base;
    if (tr > RPW) tr = RPW;

    // cp.async lane mapping: chunk = 64 rows x 32B; lane covers rows rsub+16j
    const int rsub = lane >> 1;    // 0..15
    const int sub  = lane & 1;     // 16B slot

    // ---- prologue: issue chunks 0..2 BEFORE the setup barrier (hide latency) ----
    if (tr > 0) {
        #pragma unroll
        for (int c0 = 0; c0 < 3; c0++) {
            #pragma unroll
            for (int j = 0; j < 4; j++) {
                int rl = rsub + 16 * j;
                if (rl < tr) {
                    const float* src = q + (size_t)(base + rl) * D + c0 * CHUNK + sub * 4;
                    uint32_t dst = ring_s + (uint32_t)(c0 * BUFW + rl * QSTR + sub * 4) * 4u;
                    CP16(dst, src);
                }
            }
            CPCOMMIT();
        }
    } else {
        // keep group counts uniform across warps of the block? not needed:
        // cp.async groups are per-thread; idle warps just skip.
    }

    // ---- block-cooperative setup: mem_rm (float4) + mem_t (item-pair transpose) ----
    {
        const float4* s4 = (const float4*)mem;
        float4* d4 = (float4*)mem_rm;
        #pragma unroll
        for (int i = 0; i < (MITEMS * D / 4) / TPB; i++)   // 2 iters
            d4[tid + TPB * i] = s4[tid + TPB * i];
        #pragma unroll
        for (int i = 0; i < (MITEMS * D) / TPB; i++) {     // 8 iters
            int idx = tid + TPB * i;
            mem_t[(idx & 255) * MITEMS + (idx >> 8)] = mem[idx];
        }
    }
    __syncthreads();    // the ONLY block barrier

    if (tr <= 0) return;

    // ---- dot mainloop: item-pair-packed acc (s[2p],s[2p+1] per u64) ----
    u64 accA[8], accB[8];
    u64 ssqA2 = 0ull, ssqB2 = 0ull;
    #pragma unroll
    for (int p = 0; p < 8; p++) { accA[p] = 0ull; accB[p] = 0ull; }

    #pragma unroll 1
    for (int ct = 0; ct < NCH; ct++) {
        if (ct + 2 < NCH)      { CPWAIT(2); }
        else if (ct + 1 < NCH) { CPWAIT(1); }
        else                   { CPWAIT(0); }
        __syncwarp();     // all lanes' chunk-ct copies complete

        const float* qb = ring + (ct % NBUF) * BUFW;
        #pragma unroll
        for (int h = 0; h < 2; h++) {                     // dim groups of 4
            ulonglong2 qA = *(const ulonglong2*)(qb + lane * QSTR + 4 * h);
            ulonglong2 qB = *(const ulonglong2*)(qb + (lane + 32) * QSTR + 4 * h);
            // ssq on raw dim-pairs (hsum at end)
            FMA2(ssqA2, qA.x, qA.x); FMA2(ssqA2, qA.y, qA.y);
            FMA2(ssqB2, qB.x, qB.x); FMA2(ssqB2, qB.y, qB.y);
            // broadcast-packed q scalars
            float a0, a1, a2, a3, b0, b1, b2, b3;
            unpack2(qA.x, a0, a1); unpack2(qA.y, a2, a3);
            unpack2(qB.x, b0, b1); unpack2(qB.y, b2, b3);
            u64 qqA[4] = {pack2(a0,a0), pack2(a1,a1), pack2(a2,a2), pack2(a3,a3)};
            u64 qqB[4] = {pack2(b0,b0), pack2(b1,b1), pack2(b2,b2), pack2(b3,b3)};
            #pragma unroll
            for (int d = 0; d < 4; d++) {
                const ulonglong2* mt =
                    (const ulonglong2*)(mem_t + (ct * CHUNK + 4 * h + d) * MITEMS);
                ulonglong2 v0 = mt[0], v1 = mt[1], v2 = mt[2], v3 = mt[3]; // broadcast
                FMA2(accA[0], v0.x, qqA[d]); FMA2(accA[1], v0.y, qqA[d]);
                FMA2(accA[2], v1.x, qqA[d]); FMA2(accA[3], v1.y, qqA[d]);
                FMA2(accA[4], v2.x, qqA[d]); FMA2(accA[5], v2.y, qqA[d]);
                FMA2(accA[6], v3.x, qqA[d]); FMA2(accA[7], v3.y, qqA[d]);
                FMA2(accB[0], v0.x, qqB[d]); FMA2(accB[1], v0.y, qqB[d]);
                FMA2(accB[2], v1.x, qqB[d]); FMA2(accB[3], v1.y, qqB[d]);
                FMA2(accB[4], v2.x, qqB[d]); FMA2(accB[5], v2.y, qqB[d]);
                FMA2(accB[6], v3.x, qqB[d]); FMA2(accB[7], v3.y, qqB[d]);
            }
        }
        __syncwarp();     // all lanes done reading buf ct%3
        if (ct + 3 < NCH) {   // refill it (WAR-safe: (ct+3)%3 == ct%3)
            #pragma unroll
            for (int j = 0; j < 4; j++) {
                int rl = rsub + 16 * j;
                if (rl < tr) {
                    const float* src = q + (size_t)(base + rl) * D + (ct + 3) * CHUNK + sub * 4;
                    uint32_t dst = ring_s +
                        (uint32_t)(((ct + 3) % NBUF) * BUFW + rl * QSTR + sub * 4) * 4u;
                    CP16(dst, src);
                }
            }
            CPCOMMIT();
        }
    }

    // ---- epilogue: 2 rows per lane (item pairs unpack directly to s[m]) ----
    #pragma unroll
    for (int r = 0; r < 2; r++) {
        int rl = lane + 32 * r;
        float s[MITEMS];
        #pragma unroll
        for (int p = 0; p < 8; p++)
            unpack2(r == 0 ? accA[p] : accB[p], s[2 * p], s[2 * p + 1]);
        float sl, shi; unpack2(r == 0 ? ssqA2 : ssqB2, sl, shi);
        float inv = rsqrtf(fmaxf(sl + shi, 1e-24f)) * 10.0f;  // (1/|q|)/tau; mem unit-norm
        #pragma unroll
        for (int m = 0; m < MITEMS; m++) s[m] *= inv;

        float bw[4]; int bi[4];
        #pragma unroll
        for (int k = 0; k < 4; k++) {
            float best = NEG_BIG; int b = 0;
            #pragma unroll
            for (int m = 0; m < MITEMS; m++)
                if (s[m] > best) { best = s[m]; b = m; }      // first-index ties
            bw[k] = best; bi[k] = b;
            #pragma unroll
            for (int m = 0; m < MITEMS; m++)
                s[m] = (m == b) ? NEG_BIG : s[m];
        }
        float e1 = __expf(bw[1] - bw[0]);
        float e2 = __expf(bw[2] - bw[0]);
        float e3 = __expf(bw[3] - bw[0]);
        float rden = 1.0f / (1.0f + e1 + e2 + e3);

        if (rl < tr) {
            float* Wr = pw + rl * PWSTR;
            Wr[0] = rden;
            Wr[1] = e1 * rden;
            Wr[2] = e2 * rden;
            Wr[3] = e3 * rden;
            ((int*)Wr)[4] = bi[0] | (bi[1] << 4) | (bi[2] << 8) | (bi[3] << 12);
            out_max[base + rl] = bw[0];
        }
    }
    __syncwarp();

    // ---- sparse blend: warp-per-row gathers from mem_rm (R10-proven) ----
    #pragma unroll 2
    for (int j = 0; j < RPW; j++) {
        if (j >= tr) break;
        const float* Wr = pw + j * PWSTR;
        float4 w4 = *(const float4*)Wr;          // broadcast
        int pk = ((const int*)Wr)[4];
        u64 W0 = pack2(w4.x, w4.x), W1 = pack2(w4.y, w4.y);
        u64 W2 = pack2(w4.z, w4.z), W3 = pack2(w4.w, w4.w);
        const ulonglong2* r0 = (const ulonglong2*)(mem_rm + ((pk      ) & 15) * D);
        const ulonglong2* r1 = (const ulonglong2*)(mem_rm + ((pk >> 4 ) & 15) * D);
        const ulonglong2* r2 = (const ulonglong2*)(mem_rm + ((pk >> 8 ) & 15) * D);
        const ulonglong2* r3 = (const ulonglong2*)(mem_rm + ((pk >> 12) & 15) * D);

        u64 o0 = 0ull, o1 = 0ull, o2 = 0ull, o3 = 0ull;
        ulonglong2 a;
        a = r0[lane];      FMA2(o0, a.x, W0); FMA2(o1, a.y, W0);
        a = r1[lane];      FMA2(o0, a.x, W1); FMA2(o1, a.y, W1);
        a = r2[lane];      FMA2(o0, a.x, W2); FMA2(o1, a.y, W2);
        a = r3[lane];      FMA2(o0, a.x, W3); FMA2(o1, a.y, W3);
        a = r0[32 + lane]; FMA2(o2, a.x, W0); FMA2(o3, a.y, W0);
        a = r1[32 + lane]; FMA2(o2, a.x, W1); FMA2(o3, a.y, W1);
        a = r2[32 + lane]; FMA2(o2, a.x, W2); FMA2(o3, a.y, W2);
        a = r3[32 + lane]; FMA2(o2, a.x, W3); FMA2(o3, a.y, W3);

        ulonglong2* op = (ulonglong2*)(out_ret + (size_t)(base + j) * D);
        ulonglong2 v0; v0.x = o0; v0.y = o1;
        ulonglong2 v1; v1.x = o2; v1.y = o3;
        op[lane]      = v0;
        op[32 + lane] = v1;
    }
}

extern "C" void kernel_launch(void* const* d_in, const int* in_sizes, int n_in,
                              void* d_out, int out_size)
{
    const float* q   = (const float*)d_in[0];
    const float* mem = (const float*)d_in[1];
    int nrows = in_sizes[0] / D;              // 131072
    float* out_ret = (float*)d_out;
    float* out_max = out_ret + (size_t)nrows * D;

    cudaFuncSetAttribute(epm_kernel,
                         cudaFuncAttributeMaxDynamicSharedMemorySize, SMEM_BYTES);

    epm_kernel<<<GRID, TPB, SMEM_BYTES>>>(q, mem, out_ret, out_max, nrows);
}

// round 13
// speedup vs baseline: 2.2337x; 1.0882x over previous
#include <cuda_runtime.h>
#include <stdint.h>

#define D        256
#define MITEMS   16
#define TPB      256
#define NWARP    8
#define GRID     148
#define RPW      111           // rows per warp (148*8*111 >= 131072)
#define TILE     64            // rows per warp-tile
#define CHUNK    16            // dims per pipeline chunk (64 B per row)
#define NCH      16            // D / CHUNK
#define NBUF     4
#define QSTR     20            // staging row stride (floats): LDS.128 conflict-free
#define BUFW     (TILE * QSTR) // 1280 floats per buffer
#define RINGW    (NBUF * BUFW) // 5120 floats per warp ring
#define SM_MEM   (NWARP * RINGW)           // 40960: mem_rm offset
#define SM_PW    (SM_MEM + MITEMS * D)     // 45056: dense-W offset
#define WSTR     20                         // dense-W row stride (16 w + pad, 16B-aligned)
#define SMEM_FLOATS (SM_PW + NWARP * TILE * WSTR)   // 55296 floats = 221184 B
#define SMEM_BYTES  (SMEM_FLOATS * 4)
#define NEG_BIG (-1e30f)

typedef unsigned long long u64;

__device__ __forceinline__ u64 pack2(float lo, float hi) {
    u64 r; asm("mov.b64 %0, {%1, %2};" : "=l"(r) : "f"(lo), "f"(hi)); return r;
}
__device__ __forceinline__ void unpack2(u64 v, float& lo, float& hi) {
    asm("mov.b64 {%0, %1}, %2;" : "=f"(lo), "=f"(hi) : "l"(v));
}
#define FMA2(d, a, b) asm("fma.rn.f32x2 %0, %1, %2, %0;" : "+l"(d) : "l"(a), "l"(b))
#define CP16(dst, src) \
    asm volatile("cp.async.cg.shared.global [%0], [%1], 16;" :: "r"(dst), "l"(src))
#define CPCOMMIT() asm volatile("cp.async.commit_group;")
#define CPWAIT(n)  asm volatile("cp.async.wait_group %0;" :: "n"(n))

__global__ void __launch_bounds__(TPB, 1) epm_kernel(
    const float* __restrict__ q,
    const float* __restrict__ mem,
    float* __restrict__ out_ret,
    float* __restrict__ out_max,
    int nrows)
{
    extern __shared__ __align__(16) float sh[];
    const int tid  = threadIdx.x;
    const int wid  = tid >> 5;
    const int lane = tid & 31;

    float* ring   = sh + wid * RINGW;
    float* mem_rm = sh + SM_MEM;
    float* pw     = sh + SM_PW + wid * TILE * WSTR;   // dense 16-weight rows
    const uint32_t ring_s = (uint32_t)__cvta_generic_to_shared(ring);

    // ---- block-cooperative: memory bank row-major into smem ----
    {
        const float4* s4 = (const float4*)mem;
        float4* d4 = (float4*)mem_rm;
        #pragma unroll
        for (int i = 0; i < (MITEMS * D / 4) / TPB; i++)   // 4 iters
            d4[tid + TPB * i] = s4[tid + TPB * i];
    }
    __syncthreads();    // the ONLY block barrier

    // ---- warp work assignment ----
    const int wg    = blockIdx.x * NWARP + wid;
    const int base  = wg * RPW;
    int count = nrows - base;
    if (count > RPW) count = RPW;

    // cp.async lane mapping within a 64-row tile chunk:
    const int rsub = lane >> 2;    // 0..7 (rows rsub + 8j)
    const int sub  = lane & 3;     // 16B slot within the 64B row segment

    if (count > 0) {
        for (int tb = 0; tb < count; tb += TILE) {
            const int tr    = min(TILE, count - tb);
            const int rowg0 = base + tb;

            // ---- prologue: issue chunks 0..2 into bufs 0..2 ----
            #pragma unroll
            for (int c0 = 0; c0 < 3; c0++) {
                #pragma unroll
                for (int j = 0; j < 8; j++) {
                    int rl = rsub + 8 * j;
                    if (rl < tr) {
                        const float* src = q + (size_t)(rowg0 + rl) * D + c0 * CHUNK + sub * 4;
                        uint32_t dst = ring_s +
                            (uint32_t)(c0 * BUFW + rl * QSTR + sub * 4) * 4u;
                        CP16(dst, src);
                    }
                }
                CPCOMMIT();
            }

            // ---- dot mainloop: warp-private ring, no block barriers ----
            u64 accA[MITEMS], accB[MITEMS], ssqA = 0ull, ssqB = 0ull;
            #pragma unroll
            for (int m = 0; m < MITEMS; m++) { accA[m] = 0ull; accB[m] = 0ull; }

            #pragma unroll 1
            for (int ct = 0; ct < NCH; ct++) {
                if (ct <= NCH - 3)      { CPWAIT(2); }
                else if (ct == NCH - 2) { CPWAIT(1); }
                else                    { CPWAIT(0); }
                __syncwarp();

                // refill the just-freed buffer (this warp finished reading it)
                if (ct + 3 < NCH) {
                    #pragma unroll
                    for (int j = 0; j < 8; j++) {
                        int rl = rsub + 8 * j;
                        if (rl < tr) {
                            const float* src = q + (size_t)(rowg0 + rl) * D
                                             + (ct + 3) * CHUNK + sub * 4;
                            uint32_t dst = ring_s +
                                (uint32_t)(((ct + 3) & 3) * BUFW + rl * QSTR + sub * 4) * 4u;
                            CP16(dst, src);
                        }
                    }
                    CPCOMMIT();
                }

                const float* qb = ring + (ct & 3) * BUFW;
                ulonglong2 qA[4], qB[4];
                #pragma unroll
                for (int g = 0; g < 4; g++) {
                    qA[g] = *(const ulonglong2*)(qb + lane * QSTR + 4 * g);
                    qB[g] = *(const ulonglong2*)(qb + (lane + 32) * QSTR + 4 * g);
                    FMA2(ssqA, qA[g].x, qA[g].x); FMA2(ssqA, qA[g].y, qA[g].y);
                    FMA2(ssqB, qB[g].x, qB[g].x); FMA2(ssqB, qB[g].y, qB[g].y);
                }
                #pragma unroll
                for (int m = 0; m < MITEMS; m++) {
                    const ulonglong2* mt = (const ulonglong2*)(mem_rm + m * D + ct * CHUNK);
                    ulonglong2 v0 = mt[0], v1 = mt[1], v2 = mt[2], v3 = mt[3]; // broadcast
                    FMA2(accA[m], v0.x, qA[0].x); FMA2(accA[m], v0.y, qA[0].y);
                    FMA2(accA[m], v1.x, qA[1].x); FMA2(accA[m], v1.y, qA[1].y);
                    FMA2(accA[m], v2.x, qA[2].x); FMA2(accA[m], v2.y, qA[2].y);
                    FMA2(accA[m], v3.x, qA[3].x); FMA2(accA[m], v3.y, qA[3].y);
                    FMA2(accB[m], v0.x, qB[0].x); FMA2(accB[m], v0.y, qB[0].y);
                    FMA2(accB[m], v1.x, qB[1].x); FMA2(accB[m], v1.y, qB[1].y);
                    FMA2(accB[m], v2.x, qB[2].x); FMA2(accB[m], v2.y, qB[2].y);
                    FMA2(accB[m], v3.x, qB[3].x); FMA2(accB[m], v3.y, qB[3].y);
                }
            }

            // ---- epilogue: 2 rows per lane -> dense W row (smem scatter) + out_max ----
            #pragma unroll
            for (int r = 0; r < 2; r++) {
                int rl = lane + 32 * r;
                float s[MITEMS];
                #pragma unroll
                for (int m = 0; m < MITEMS; m++) {
                    float lo, hi; unpack2(r == 0 ? accA[m] : accB[m], lo, hi);
                    s[m] = lo + hi;
                }
                float sl, shi; unpack2(r == 0 ? ssqA : ssqB, sl, shi);
                float inv = rsqrtf(fmaxf(sl + shi, 1e-24f)) * 10.0f; // (1/|q|)/tau
                #pragma unroll
                for (int m = 0; m < MITEMS; m++) s[m] *= inv;

                float bw[4]; int bi[4];
                #pragma unroll
                for (int k = 0; k < 4; k++) {
                    float best = NEG_BIG; int b = 0;
                    #pragma unroll
                    for (int m = 0; m < MITEMS; m++)
                        if (s[m] > best) { best = s[m]; b = m; }  // first-index ties
                    bw[k] = best; bi[k] = b;
                    #pragma unroll
                    for (int m = 0; m < MITEMS; m++)
                        s[m] = (m == b) ? NEG_BIG : s[m];
                }
                float e1 = __expf(bw[1] - bw[0]);
                float e2 = __expf(bw[2] - bw[0]);
                float e3 = __expf(bw[3] - bw[0]);
                float rden = 1.0f / (1.0f + e1 + e2 + e3);

                if (rl < tr) {
                    float* Wr = pw + rl * WSTR;
                    float4 z = make_float4(0.f, 0.f, 0.f, 0.f);
                    ((float4*)Wr)[0] = z;
                    ((float4*)Wr)[1] = z;
                    ((float4*)Wr)[2] = z;
                    ((float4*)Wr)[3] = z;
                    // dynamic-address SMEM scatter (memory, not registers: safe)
                    Wr[bi[0]] = rden;
                    Wr[bi[1]] = e1 * rden;
                    Wr[bi[2]] = e2 * rden;
                    Wr[bi[3]] = e3 * rden;
                    out_max[rowg0 + rl] = bw[0];
                }
            }
            __syncwarp();

            // ---- dense blend: V register-resident, 4 broadcast wf per row ----
            {
                ulonglong2 V[2 * MITEMS];     // acc regs dead -> reused by allocator
                const ulonglong2* mg = (const ulonglong2*)mem_rm;
                #pragma unroll
                for (int m = 0; m < MITEMS; m++) {
                    V[2 * m    ] = mg[m * (D / 4) + lane];       // dims 4*lane..
                    V[2 * m + 1] = mg[m * (D / 4) + 32 + lane];  // dims 128+4*lane..
                }

                #pragma unroll 2
                for (int j = 0; j < TILE; j++) {
                    if (j >= tr) break;
                    const float4* Wp = (const float4*)(pw + j * WSTR);  // broadcasts
                    float4 w0 = Wp[0], w1 = Wp[1], w2 = Wp[2], w3 = Wp[3];
                    float wv[16] = {w0.x, w0.y, w0.z, w0.w, w1.x, w1.y, w1.z, w1.w,
                                    w2.x, w2.y, w2.z, w2.w, w3.x, w3.y, w3.z, w3.w};
                    u64 o0 = 0ull, o1 = 0ull, o2 = 0ull, o3 = 0ull;
                    #pragma unroll
                    for (int m = 0; m < MITEMS; m++) {       // static indexing only
                        u64 wm = pack2(wv[m], wv[m]);
                        FMA2(o0, V[2 * m    ].x, wm);
                        FMA2(o1, V[2 * m    ].y, wm);
                        FMA2(o2, V[2 * m + 1].x, wm);
                        FMA2(o3, V[2 * m + 1].y, wm);
                    }
                    ulonglong2* op = (ulonglong2*)(out_ret + (size_t)(rowg0 + j) * D);
                    ulonglong2 v0; v0.x = o0; v0.y = o1;
                    ulonglong2 v1; v1.x = o2; v1.y = o3;
                    op[lane]      = v0;
                    op[32 + lane] = v1;
                }
            }
            __syncwarp();
        }
    }
}

extern "C" void kernel_launch(void* const* d_in, const int* in_sizes, int n_in,
                              void* d_out, int out_size)
{
    const float* q   = (const float*)d_in[0];
    const float* mem = (const float*)d_in[1];
    int nrows = in_sizes[0] / D;              // 131072
    float* out_ret = (float*)d_out;
    float* out_max = out_ret + (size_t)nrows * D;

    cudaFuncSetAttribute(epm_kernel,
                         cudaFuncAttributeMaxDynamicSharedMemorySize, SMEM_BYTES);

    epm_kernel<<<GRID, TPB, SMEM_BYTES>>>(q, mem, out_ret, out_max, nrows);
}